// round 10
// baseline (speedup 1.0000x reference)
#include <cuda_runtime.h>

// SNNReadout: out[t,b,c] = LIF-scan over t of (2 * sum_f spike[t,b,f]*mask[t,b,f]*W[c,f] + b[c])
// T=100, B=128, F=4096, C=10. HBM-bound: 420 MB streaming reads. fp32 exactness
// required by the Heaviside threshold -> no tensor cores; packed f32x2 FMA.
//
// GEMM: W (160 KB) fully resident in smem, grid=152 (one exact wave), row pairs,
// and a software-pipelined stream: next slice's 4 LDG.128 issued before current
// slice's FMAs, keeping loads in flight through compute phases.

#define T_STEPS 100
#define BATCH   128
#define FDIM    4096
#define CDIM    10
#define MROWS   (T_STEPS * BATCH)      // 12800
#define NCHAINS (BATCH * CDIM)         // 1280
#define NSLICE  (FDIM / 128)           // 32

#define GEMM_GRID 152                  // GB300: 152 SMs, occ 1 -> one exact wave
#define GEMM_TPB  512
#define WARPS_TOT (GEMM_GRID * (GEMM_TPB / 32))   // 2432
#define SW_BYTES  (CDIM * FDIM * 4)    // 160 KB

#define SCAN_PF   12                   // scan prefetch depth (covers L2 latency)

typedef unsigned long long u64;

__device__ float g_current[MROWS * CDIM];   // 512 KB scratch (no allocation allowed)

__device__ __forceinline__ u64 mul2(u64 a, u64 b) {
    u64 d; asm("mul.rn.f32x2 %0, %1, %2;" : "=l"(d) : "l"(a), "l"(b)); return d;
}
__device__ __forceinline__ u64 fma2(u64 a, u64 b, u64 c) {
    u64 d; asm("fma.rn.f32x2 %0, %1, %2, %3;" : "=l"(d) : "l"(a), "l"(b), "l"(c)); return d;
}
__device__ __forceinline__ ulonglong2 ldcs128(const float* p) {
    ulonglong2 r;
    asm("ld.global.cs.v2.b64 {%0, %1}, [%2];" : "=l"(r.x), "=l"(r.y) : "l"(p));
    return r;
}
__device__ __forceinline__ float sum2(u64 a) {
    float lo, hi;
    asm("mov.b64 {%0, %1}, %2;" : "=f"(lo), "=f"(hi) : "l"(a));
    return lo + hi;
}
__device__ __forceinline__ float warp_red_keep(float v, int lane, int c, float cur) {
    #pragma unroll
    for (int off = 16; off > 0; off >>= 1)
        v += __shfl_xor_sync(0xFFFFFFFFu, v, off);
    return (lane == c) ? v : cur;
}

struct Batch { ulonglong2 s0, m0, s1, m1; };   // one 128-float slice, 2 rows

__device__ __forceinline__ Batch load_batch(const float* sp, const float* mp, int fl) {
    Batch b;
    b.s0 = ldcs128(sp + fl);
    b.m0 = ldcs128(mp + fl);
    b.s1 = ldcs128(sp + FDIM + fl);
    b.m1 = ldcs128(mp + FDIM + fl);
    return b;
}

__device__ __forceinline__ void consume_batch(const Batch& b, u64 acc[2][CDIM],
                                              const float* sW, int fl) {
    const u64 x00 = mul2(b.s0.x, b.m0.x);
    const u64 x01 = mul2(b.s0.y, b.m0.y);
    const u64 x10 = mul2(b.s1.x, b.m1.x);
    const u64 x11 = mul2(b.s1.y, b.m1.y);
    #pragma unroll
    for (int c = 0; c < CDIM; ++c) {
        const ulonglong2 w = *((const ulonglong2*)(sW + c * FDIM + fl));  // LDS.128
        acc[0][c] = fma2(x00, w.x, acc[0][c]);
        acc[0][c] = fma2(x01, w.y, acc[0][c]);
        acc[1][c] = fma2(x10, w.x, acc[1][c]);
        acc[1][c] = fma2(x11, w.y, acc[1][c]);
    }
}

__global__ __launch_bounds__(GEMM_TPB, 1)
void snn_gemm_kernel(const float* __restrict__ spk,
                     const float* __restrict__ msk,
                     const float* __restrict__ W,
                     const float* __restrict__ bias) {
    extern __shared__ float sW[];      // 160 KB: full W[c][f]

    const int tid  = threadIdx.x;
    const int warp = tid >> 5;
    const int lane = tid & 31;

    for (int i = tid; i < CDIM * FDIM / 4; i += GEMM_TPB)
        ((float4*)sW)[i] = __ldg((const float4*)W + i);
    __syncthreads();

    const float bv = (lane < CDIM) ? __ldg(bias + lane) : 0.0f;

    // Balanced contiguous row range for this warp (5 or 6 rows)
    const int gw   = blockIdx.x * (GEMM_TPB / 32) + warp;
    int       row  = (int)((long long)gw * MROWS / WARPS_TOT);
    const int rend = (int)((long long)(gw + 1) * MROWS / WARPS_TOT);

    // ---- row pairs, software-pipelined stream ----
    for (; row + 2 <= rend; row += 2) {
        const float* sp0 = spk + (size_t)row * FDIM;
        const float* mp0 = msk + (size_t)row * FDIM;

        u64 acc[2][CDIM];
        #pragma unroll
        for (int r = 0; r < 2; ++r)
            #pragma unroll
            for (int c = 0; c < CDIM; ++c) acc[r][c] = 0ULL;

        const int fl0 = lane * 4;
        Batch P = load_batch(sp0, mp0, fl0);           // prologue: slice 0 in flight

        #pragma unroll 4
        for (int q = 0; q < NSLICE - 1; ++q) {
            Batch N = load_batch(sp0, mp0, fl0 + (q + 1) * 128);  // next slice airborne
            consume_batch(P, acc, sW, fl0 + q * 128);             // while FMAs run
            P = N;
        }
        consume_batch(P, acc, sW, fl0 + (NSLICE - 1) * 128);      // epilogue

        #pragma unroll
        for (int r = 0; r < 2; ++r) {
            float outv = 0.0f;
            #pragma unroll
            for (int c = 0; c < CDIM; ++c)
                outv = warp_red_keep(sum2(acc[r][c]), lane, c, outv);
            if (lane < CDIM)
                g_current[(size_t)(row + r) * CDIM + lane] = 2.0f * outv + bv;
        }
    }

    // ---- leftover single row ----
    if (row < rend) {
        const float* sp0 = spk + (size_t)row * FDIM;
        const float* mp0 = msk + (size_t)row * FDIM;

        u64 acc[CDIM];
        #pragma unroll
        for (int c = 0; c < CDIM; ++c) acc[c] = 0ULL;

        #pragma unroll 1
        for (int q = 0; q < NSLICE; q += 4) {          // 4 slices -> 8 LDG.128 batched
            const int fl0 = q * 128 + lane * 4;
            ulonglong2 s[4], m[4];
            #pragma unroll
            for (int u = 0; u < 4; ++u) {
                s[u] = ldcs128(sp0 + fl0 + u * 128);
                m[u] = ldcs128(mp0 + fl0 + u * 128);
            }
            #pragma unroll
            for (int u = 0; u < 4; ++u) {
                const int fl = fl0 + u * 128;
                const u64 x0 = mul2(s[u].x, m[u].x);
                const u64 x1 = mul2(s[u].y, m[u].y);
                #pragma unroll
                for (int c = 0; c < CDIM; ++c) {
                    const ulonglong2 w = *((const ulonglong2*)(sW + c * FDIM + fl));
                    acc[c] = fma2(x0, w.x, acc[c]);
                    acc[c] = fma2(x1, w.y, acc[c]);
                }
            }
        }
        float outv = 0.0f;
        #pragma unroll
        for (int c = 0; c < CDIM; ++c)
            outv = warp_red_keep(sum2(acc[c]), lane, c, outv);
        if (lane < CDIM)
            g_current[(size_t)row * CDIM + lane] = 2.0f * outv + bv;
    }
}

// LIF scan: one thread per chain, fully-unrolled t-loop with a 12-deep static
// register ring buffer: LDG for t+12 issued at t, so the L2 latency is covered
// by 12 iterations of the dependent ALU chain. No smem, no sync.
__global__ __launch_bounds__(128)
void snn_scan_kernel(float* __restrict__ out) {
    const int idx = blockIdx.x * 128 + threadIdx.x;    // 10 blocks x 128 = 1280

    const float* gc = g_current + idx;
    float buf[SCAN_PF];
    #pragma unroll
    for (int k = 0; k < SCAN_PF; ++k)
        buf[k] = __ldg(gc + k * NCHAINS);

    float v = 0.0f;
    #pragma unroll
    for (int t = 0; t < T_STEPS; ++t) {
        const float cur = buf[t % SCAN_PF];
        if (t + SCAN_PF < T_STEPS)
            buf[t % SCAN_PF] = __ldg(gc + (t + SCAN_PF) * NCHAINS);
        v = fmaf(v, 0.9f, cur);                        // v*BETA + current
        const float s = (v > 1.0f) ? 1.0f : 0.0f;      // Heaviside(v - V_TH)
        out[t * NCHAINS + idx] = s;
        v -= s;                                        // soft reset
    }
}

extern "C" void kernel_launch(void* const* d_in, const int* in_sizes, int n_in,
                              void* d_out, int out_size) {
    const float* spk  = (const float*)d_in[0];  // spike_seq [T,B,F]
    const float* msk  = (const float*)d_in[1];  // drop_mask [T,B,F]
    const float* W    = (const float*)d_in[2];  // W [C,F]
    const float* bias = (const float*)d_in[3];  // b [C]
    float* out = (float*)d_out;                 // out_spikes [T,B,C] fp32

    // Non-stream API: capture-safe; also runs on the uncaptured correctness call.
    cudaFuncSetAttribute(snn_gemm_kernel,
                         cudaFuncAttributeMaxDynamicSharedMemorySize, SW_BYTES);

    snn_gemm_kernel<<<GEMM_GRID, GEMM_TPB, SW_BYTES>>>(spk, msk, W, bias);
    snn_scan_kernel<<<NCHAINS / 128, 128>>>(out);
}

// round 12
// speedup vs baseline: 1.0215x; 1.0215x over previous
#include <cuda_runtime.h>

// SNNReadout: out[t,b,c] = LIF-scan over t of (2 * sum_f spike[t,b,f]*mask[t,b,f]*W[c,f] + b[c])
// T=100, B=128, F=4096, C=10. HBM-bound: 420 MB streaming reads. fp32 exactness
// required by the Heaviside threshold -> no tensor cores; packed f32x2 FMA.
//
// GEMM: W (160 KB) fully resident in smem, grid=152 (one exact wave), row pairs,
// depth-2 software pipeline: slices q+1,q+2 in flight while slice q's FMAs run
// (Little's law: need ~31 KB/SM in flight to cover ~600cyc DRAM latency).

#define T_STEPS 100
#define BATCH   128
#define FDIM    4096
#define CDIM    10
#define MROWS   (T_STEPS * BATCH)      // 12800
#define NCHAINS (BATCH * CDIM)         // 1280
#define NSLICE  (FDIM / 128)           // 32
#define SCAN_CPB 64                    // chains per scan block -> 20 blocks

#define GEMM_GRID 152                  // GB300: 152 SMs, occ 1 -> one exact wave
#define GEMM_TPB  512
#define WARPS_TOT (GEMM_GRID * (GEMM_TPB / 32))   // 2432
#define SW_BYTES  (CDIM * FDIM * 4)    // 160 KB

typedef unsigned long long u64;

__device__ float g_current[MROWS * CDIM];   // 512 KB scratch (no allocation allowed)

__device__ __forceinline__ u64 mul2(u64 a, u64 b) {
    u64 d; asm("mul.rn.f32x2 %0, %1, %2;" : "=l"(d) : "l"(a), "l"(b)); return d;
}
__device__ __forceinline__ u64 fma2(u64 a, u64 b, u64 c) {
    u64 d; asm("fma.rn.f32x2 %0, %1, %2, %3;" : "=l"(d) : "l"(a), "l"(b), "l"(c)); return d;
}
__device__ __forceinline__ ulonglong2 ldcs128(const float* p) {
    ulonglong2 r;
    asm("ld.global.cs.v2.b64 {%0, %1}, [%2];" : "=l"(r.x), "=l"(r.y) : "l"(p));
    return r;
}
__device__ __forceinline__ float sum2(u64 a) {
    float lo, hi;
    asm("mov.b64 {%0, %1}, %2;" : "=f"(lo), "=f"(hi) : "l"(a));
    return lo + hi;
}
__device__ __forceinline__ float warp_red_keep(float v, int lane, int c, float cur) {
    #pragma unroll
    for (int off = 16; off > 0; off >>= 1)
        v += __shfl_xor_sync(0xFFFFFFFFu, v, off);
    return (lane == c) ? v : cur;
}

struct Batch { ulonglong2 s0, m0, s1, m1; };   // one 128-float slice, 2 rows

__device__ __forceinline__ Batch load_batch(const float* sp, const float* mp, int fl) {
    Batch b;
    b.s0 = ldcs128(sp + fl);
    b.m0 = ldcs128(mp + fl);
    b.s1 = ldcs128(sp + FDIM + fl);
    b.m1 = ldcs128(mp + FDIM + fl);
    return b;
}

__device__ __forceinline__ void consume_batch(const Batch& b, u64 acc[2][CDIM],
                                              const float* sW, int fl) {
    const u64 x00 = mul2(b.s0.x, b.m0.x);
    const u64 x01 = mul2(b.s0.y, b.m0.y);
    const u64 x10 = mul2(b.s1.x, b.m1.x);
    const u64 x11 = mul2(b.s1.y, b.m1.y);
    #pragma unroll
    for (int c = 0; c < CDIM; ++c) {
        const ulonglong2 w = *((const ulonglong2*)(sW + c * FDIM + fl));  // LDS.128
        acc[0][c] = fma2(x00, w.x, acc[0][c]);
        acc[0][c] = fma2(x01, w.y, acc[0][c]);
        acc[1][c] = fma2(x10, w.x, acc[1][c]);
        acc[1][c] = fma2(x11, w.y, acc[1][c]);
    }
}

__global__ __launch_bounds__(GEMM_TPB, 1)
void snn_gemm_kernel(const float* __restrict__ spk,
                     const float* __restrict__ msk,
                     const float* __restrict__ W,
                     const float* __restrict__ bias) {
    extern __shared__ float sW[];      // 160 KB: full W[c][f]

    const int tid  = threadIdx.x;
    const int warp = tid >> 5;
    const int lane = tid & 31;

    for (int i = tid; i < CDIM * FDIM / 4; i += GEMM_TPB)
        ((float4*)sW)[i] = __ldg((const float4*)W + i);
    __syncthreads();

    const float bv = (lane < CDIM) ? __ldg(bias + lane) : 0.0f;

    // Balanced contiguous row range for this warp (5 or 6 rows)
    const int gw   = blockIdx.x * (GEMM_TPB / 32) + warp;
    int       row  = (int)((long long)gw * MROWS / WARPS_TOT);
    const int rend = (int)((long long)(gw + 1) * MROWS / WARPS_TOT);

    // ---- row pairs, depth-2 software pipeline ----
    for (; row + 2 <= rend; row += 2) {
        const float* sp0 = spk + (size_t)row * FDIM;
        const float* mp0 = msk + (size_t)row * FDIM;

        u64 acc[2][CDIM];
        #pragma unroll
        for (int r = 0; r < 2; ++r)
            #pragma unroll
            for (int c = 0; c < CDIM; ++c) acc[r][c] = 0ULL;

        const int fl0 = lane * 4;
        Batch P0 = load_batch(sp0, mp0, fl0);            // slices 0,1 in flight
        Batch P1 = load_batch(sp0, mp0, fl0 + 128);

        #pragma unroll 4
        for (int q = 0; q < NSLICE - 2; ++q) {
            Batch N = load_batch(sp0, mp0, fl0 + (q + 2) * 128);  // q+2 airborne
            consume_batch(P0, acc, sW, fl0 + q * 128);            // while FMAs run
            P0 = P1;
            P1 = N;
        }
        consume_batch(P0, acc, sW, fl0 + (NSLICE - 2) * 128);
        consume_batch(P1, acc, sW, fl0 + (NSLICE - 1) * 128);

        #pragma unroll
        for (int r = 0; r < 2; ++r) {
            float outv = 0.0f;
            #pragma unroll
            for (int c = 0; c < CDIM; ++c)
                outv = warp_red_keep(sum2(acc[r][c]), lane, c, outv);
            if (lane < CDIM)
                g_current[(size_t)(row + r) * CDIM + lane] = 2.0f * outv + bv;
        }
    }

    // ---- leftover single row ----
    if (row < rend) {
        const float* sp0 = spk + (size_t)row * FDIM;
        const float* mp0 = msk + (size_t)row * FDIM;

        u64 acc[CDIM];
        #pragma unroll
        for (int c = 0; c < CDIM; ++c) acc[c] = 0ULL;

        #pragma unroll 1
        for (int q = 0; q < NSLICE; q += 4) {          // 4 slices -> 8 LDG.128 batched
            const int fl0 = q * 128 + lane * 4;
            ulonglong2 s[4], m[4];
            #pragma unroll
            for (int u = 0; u < 4; ++u) {
                s[u] = ldcs128(sp0 + fl0 + u * 128);
                m[u] = ldcs128(mp0 + fl0 + u * 128);
            }
            #pragma unroll
            for (int u = 0; u < 4; ++u) {
                const int fl = fl0 + u * 128;
                const u64 x0 = mul2(s[u].x, m[u].x);
                const u64 x1 = mul2(s[u].y, m[u].y);
                #pragma unroll
                for (int c = 0; c < CDIM; ++c) {
                    const ulonglong2 w = *((const ulonglong2*)(sW + c * FDIM + fl));
                    acc[c] = fma2(x0, w.x, acc[c]);
                    acc[c] = fma2(x1, w.y, acc[c]);
                }
            }
        }
        float outv = 0.0f;
        #pragma unroll
        for (int c = 0; c < CDIM; ++c)
            outv = warp_red_keep(sum2(acc[c]), lane, c, outv);
        if (lane < CDIM)
            g_current[(size_t)row * CDIM + lane] = 2.0f * outv + bv;
    }
}

// LIF scan (Round-7 measured-best version, 6.78us): stage each block's 64
// chains x 100 steps in smem via one bulk MLP burst, then pure ALU chain.
__global__ __launch_bounds__(SCAN_CPB)
void snn_scan_kernel(float* __restrict__ out) {
    __shared__ float scur[T_STEPS * SCAN_CPB];       // 25.6 KB

    const int tid  = threadIdx.x;
    const int base = blockIdx.x * SCAN_CPB;          // first chain of this block

    // Bulk load: 100 t-rows x 16 float4 per block = 1600 independent LDG.128.
    const float4* gc4 = (const float4*)g_current;
    #pragma unroll 8
    for (int i = tid; i < T_STEPS * (SCAN_CPB / 4); i += SCAN_CPB) {
        const int t = i / (SCAN_CPB / 4);
        const int j = i % (SCAN_CPB / 4);
        ((float4*)scur)[t * (SCAN_CPB / 4) + j] =
            gc4[(t * NCHAINS + base) / 4 + j];
    }
    __syncthreads();

    float v = 0.0f;
    #pragma unroll
    for (int t = 0; t < T_STEPS; ++t) {
        const float cur = scur[t * SCAN_CPB + tid];  // conflict-free LDS
        v = fmaf(v, 0.9f, cur);                      // v*BETA + current
        const float s = (v > 1.0f) ? 1.0f : 0.0f;    // Heaviside(v - V_TH)
        out[t * NCHAINS + base + tid] = s;
        v -= s;                                      // soft reset
    }
}

extern "C" void kernel_launch(void* const* d_in, const int* in_sizes, int n_in,
                              void* d_out, int out_size) {
    const float* spk  = (const float*)d_in[0];  // spike_seq [T,B,F]
    const float* msk  = (const float*)d_in[1];  // drop_mask [T,B,F]
    const float* W    = (const float*)d_in[2];  // W [C,F]
    const float* bias = (const float*)d_in[3];  // b [C]
    float* out = (float*)d_out;                 // out_spikes [T,B,C] fp32

    // Non-stream API: capture-safe; also runs on the uncaptured correctness call.
    cudaFuncSetAttribute(snn_gemm_kernel,
                         cudaFuncAttributeMaxDynamicSharedMemorySize, SW_BYTES);

    snn_gemm_kernel<<<GEMM_GRID, GEMM_TPB, SW_BYTES>>>(spk, msk, W, bias);
    snn_scan_kernel<<<NCHAINS / SCAN_CPB, SCAN_CPB>>>(out);
}